// round 9
// baseline (speedup 1.0000x reference)
#include <cuda_runtime.h>
#include <cuda_fp16.h>

// Fixed problem shape
#define BB   2048
#define TTN  2048
#define HH   51
#define RPB  16          // batch rows per block
#define NBLK 128
#define NTHR 256
#define GT   204         // gate threads: c2 in [0,102) x rh in [0,2); G=2 gates, R=8 rows

typedef unsigned long long u64;

__device__ __forceinline__ u64 pk2(float a) {
    u64 r; asm("mov.b64 %0, {%1, %1};" : "=l"(r) : "f"(a)); return r;
}
__device__ __forceinline__ u64 fma2(u64 a, u64 b, u64 c) {
    u64 d; asm("fma.rn.f32x2 %0, %1, %2, %3;" : "=l"(d) : "l"(a), "l"(b), "l"(c)); return d;
}
union U2 { u64 v; float2 f; };

__device__ __forceinline__ float sigx(float x)  { return __fdividef(1.0f, 1.0f + __expf(-x)); }
__device__ __forceinline__ float tanhx(float x) { return __fdividef(2.0f, 1.0f + __expf(-2.0f * x)) - 1.0f; }

// ---------------- smem layout (float-slot offsets) ----------------
// W1p : 102 rows x 27 float4  {w(g0,km),w(g1,km),w(g0,km+1),w(g1,km+1)}, kp 0..25 data (fp32)
// W2p : 102 rows x 53 float4  kp 0..51 data; zero at km=51 (x slot) and km=103 (fp32)
// gbA/gbB : u64 gate buffers, idx (rpg*51+u)*5 + g (g=0..3, slot4 pad); 2040 u64 each
// hcH : half2 [rowpair 0..7][k 0..105]; k: 0..50 h1, 51 x, 52..102 h2, 103..105 pad
#define W1P_OFF 0
#define W2P_OFF 11016
#define GBA_OFF 32640
#define GBB_OFF 36720
#define HC_OFF  40800
#define BS1_OFF 41648
#define BS2_OFF 41856
#define WLS_OFF 42064
#define SM_TOT  42128

__device__ __forceinline__ void gate_accum(const float4* __restrict__ wp,
                                           const __half2* __restrict__ hb,   // hcH + rh*4*106
                                           int kp0, int kp1, U2 acc[2][4]) {
    #pragma unroll 2
    for (int kp = kp0; kp < kp1; kp++) {
        float4 w4 = wp[kp];
        int km = kp << 1;
        u64 w0a = pk2(w4.x), w1a = pk2(w4.y);   // gates g0,g1 @ km
        u64 w0b = pk2(w4.z), w1b = pk2(w4.w);   // gates g0,g1 @ km+1
        #pragma unroll
        for (int rp = 0; rp < 4; rp++) {
            uint2 q = *reinterpret_cast<const uint2*>(hb + rp * 106 + km);
            __half2 ha = *reinterpret_cast<const __half2*>(&q.x);   // 2 rows @ km
            __half2 hc = *reinterpret_cast<const __half2*>(&q.y);   // 2 rows @ km+1
            U2 fa, fb;
            fa.f = __half22float2(ha);
            fb.f = __half22float2(hc);
            acc[0][rp].v = fma2(w0a, fa.v, acc[0][rp].v);
            acc[1][rp].v = fma2(w1a, fa.v, acc[1][rp].v);
            acc[0][rp].v = fma2(w0b, fb.v, acc[0][rp].v);
            acc[1][rp].v = fma2(w1b, fb.v, acc[1][rp].v);
        }
    }
}

__device__ __forceinline__ void gbuf_store(u64* gb, int c2, int rh, U2 acc[2][4]) {
    int u = c2 >> 1, g0 = (c2 & 1) * 2;
    #pragma unroll
    for (int rp = 0; rp < 4; rp++) {
        int rpg = rh * 4 + rp;
        gb[(rpg * 51 + u) * 5 + g0]     = acc[0][rp].v;
        gb[(rpg * 51 + u) * 5 + g0 + 1] = acc[1][rp].v;
    }
}

__device__ __forceinline__ float cellstep(float gi, float gf, float gg, float go, float& c) {
    float cn = sigx(gf) * c + sigx(gi) * tanhx(gg);
    c = cn;
    return sigx(go) * tanhx(cn);
}

__global__ __launch_bounds__(NTHR, 1)
void lstm2_kernel(const float* __restrict__ input,
                  const float* __restrict__ Wih1, const float* __restrict__ Whh1,
                  const float* __restrict__ bih1, const float* __restrict__ bhh1,
                  const float* __restrict__ Wih2, const float* __restrict__ Whh2,
                  const float* __restrict__ bih2, const float* __restrict__ bhh2,
                  const float* __restrict__ Wlin, const float* __restrict__ blin,
                  float* __restrict__ out)
{
    extern __shared__ float sm[];
    const int tid  = threadIdx.x;
    const int row0 = blockIdx.x * RPB;

    float4*  W1p4 = reinterpret_cast<float4*>(sm + W1P_OFF);
    float4*  W2p4 = reinterpret_cast<float4*>(sm + W2P_OFF);
    u64*     gbA  = reinterpret_cast<u64*>(sm + GBA_OFF);
    u64*     gbB  = reinterpret_cast<u64*>(sm + GBB_OFF);
    __half2* hcH  = reinterpret_cast<__half2*>(sm + HC_OFF);
    float*   bs1  = sm + BS1_OFF;
    float*   bs2  = sm + BS2_OFF;
    float*   wls  = sm + WLS_OFF;

    // ---------------- staging (weights fp32) ----------------
    for (int q = tid; q < 102 * 27; q += NTHR) {
        int c2i = q / 27, kp = q % 27;
        int u = c2i >> 1, g0 = (c2i & 1) * 2;
        float4 v = make_float4(0.f, 0.f, 0.f, 0.f);
        if (kp < 26) {
            int km0 = 2 * kp, km1 = km0 + 1;
            int r0 = g0 * HH + u, r1 = (g0 + 1) * HH + u;
            v.x = (km0 < HH) ? Whh1[r0 * HH + km0] : Wih1[r0];
            v.y = (km0 < HH) ? Whh1[r1 * HH + km0] : Wih1[r1];
            v.z = (km1 < HH) ? Whh1[r0 * HH + km1] : Wih1[r0];
            v.w = (km1 < HH) ? Whh1[r1 * HH + km1] : Wih1[r1];
        }
        W1p4[q] = v;
    }
    for (int q = tid; q < 102 * 53; q += NTHR) {
        int c2i = q / 53, kp = q % 53;
        int u = c2i >> 1, g0 = (c2i & 1) * 2;
        float4 v = make_float4(0.f, 0.f, 0.f, 0.f);
        if (kp < 52) {
            int r0 = g0 * HH + u, r1 = (g0 + 1) * HH + u;
            int km0 = 2 * kp, km1 = km0 + 1;
            #define W2VAL(r, km) ((km) < HH ? Wih2[(r) * HH + (km)] : \
                                  ((km) == HH ? 0.0f : ((km) <= 102 ? Whh2[(r) * HH + ((km) - 52)] : 0.0f)))
            v.x = W2VAL(r0, km0); v.y = W2VAL(r1, km0);
            v.z = W2VAL(r0, km1); v.w = W2VAL(r1, km1);
            #undef W2VAL
        }
        W2p4[q] = v;
    }
    for (int c = tid; c < 208; c += NTHR) {
        if (c < 204) {
            int u = c >> 2, g = c & 3, j = g * HH + u;
            bs1[c] = bih1[j] + bhh1[j];
            bs2[c] = bih2[j] + bhh2[j];
        } else { bs1[c] = 0.f; bs2[c] = 0.f; }
    }
    if (tid < HH) wls[tid] = Wlin[tid];
    for (int i = tid; i < 8 * 106; i += NTHR) hcH[i] = __floats2half2_rn(0.f, 0.f);
    __syncthreads();
    if (tid < 8)
        hcH[tid * 106 + 51] = __floats2half2_rn(input[(row0 + 2 * tid) * TTN],
                                                input[(row0 + 2 * tid + 1) * TTN]);
    __syncthreads();

    // ---------------- roles ----------------
    const bool cw = (tid < GT);
    const int  c2 = tid >> 1, rh = tid & 1;       // gate coords: 2 gates x 8 rows
    const int  au = tid % HH, ap = tid / HH;      // act coords: unit au, rowpair-pair ap (0..3)
    const bool yw = (tid >= 224 && tid < 240);
    const int  yr = tid - 224;
    const bool xw = (tid >= 240 && tid < 248);
    const int  xp = tid - 240;

    const float4*  w1p = W1p4 + c2 * 27;
    const float4*  w2p = W2p4 + c2 * 53;
    const __half2* hb  = hcH + (rh * 4) * 106;

    float c1s[4] = {0.f, 0.f, 0.f, 0.f};          // cell state: 2 rowpairs x 2 rows
    float c2s[4] = {0.f, 0.f, 0.f, 0.f};
    U2 acc[2][4];
    const float ybias = blin[0];

    float2 xa = make_float2(0.f, 0.f);
    if (xw) xa = make_float2(input[(row0 + 2 * xp) * TTN + 1],
                             input[(row0 + 2 * xp + 1) * TTN + 1]);

    // ---------------- prolog: L1 gates for t=0 -> gbA ----------------
    if (cw) {
        acc[0][0].v = acc[0][1].v = acc[0][2].v = acc[0][3].v = pk2(bs1[2 * c2]);
        acc[1][0].v = acc[1][1].v = acc[1][2].v = acc[1][3].v = pk2(bs1[2 * c2 + 1]);
        gate_accum(w1p, hb, 0, 26, acc);
        gbuf_store(gbA, c2, rh, acc);
    }
    __syncthreads();

    // ---------------- main loop: 3 barriers/step ----------------
    for (int t = 0; t < TTN; t++) {
        // === P1: act1 (gbA) -> h1 (fp16); L2 partial over old h2; y_{t-1} ===
        if (cw) {
            #pragma unroll
            for (int s = 0; s < 2; s++) {
                int rpg = 2 * ap + s;
                const u64* gp = gbA + (rpg * 51 + au) * 5;
                U2 gi, gf, gG, go;
                gi.v = gp[0]; gf.v = gp[1]; gG.v = gp[2]; go.v = gp[3];
                float* cs = c1s + 2 * s;
                float h0 = cellstep(gi.f.x, gf.f.x, gG.f.x, go.f.x, cs[0]);
                float h1 = cellstep(gi.f.y, gf.f.y, gG.f.y, go.f.y, cs[1]);
                hcH[rpg * 106 + au] = __floats2half2_rn(h0, h1);
            }
            acc[0][0].v = acc[0][1].v = acc[0][2].v = acc[0][3].v = pk2(bs2[2 * c2]);
            acc[1][0].v = acc[1][1].v = acc[1][2].v = acc[1][3].v = pk2(bs2[2 * c2 + 1]);
            gate_accum(w2p, hb, 26, 52, acc);   // km 52..103: old h2 (+ zero pad)
        } else if (yw && t > 0) {
            const __half2* h2p = hcH + (yr >> 1) * 106 + 52;
            const int sel = yr & 1;
            float y = ybias;
            #pragma unroll 3
            for (int u = 0; u < HH; u++) {
                float2 f = __half22float2(h2p[u]);
                y += (sel ? f.y : f.x) * wls[u];
            }
            out[(row0 + yr) * TTN + (t - 1)] = y;
        }
        __syncthreads();

        // === P2: L2 rest over new h1 (+x slot, zero weight) -> gbB ===
        if (cw) {
            gate_accum(w2p, hb, 0, 26, acc);    // km 0..51
            gbuf_store(gbB, c2, rh, acc);
        } else if (xw) {
            hcH[xp * 106 + 51] = __floats2half2_rn(xa.x, xa.y);   // publish x_{t+1}
            if (t + 2 < TTN)
                xa = make_float2(input[(row0 + 2 * xp) * TTN + t + 2],
                                 input[(row0 + 2 * xp + 1) * TTN + t + 2]);
        }
        __syncthreads();

        // === P3: act2 (gbB) -> h2 (fp16); L1 gates for t+1 -> gbA ===
        if (cw) {
            #pragma unroll
            for (int s = 0; s < 2; s++) {
                int rpg = 2 * ap + s;
                const u64* gp = gbB + (rpg * 51 + au) * 5;
                U2 gi, gf, gG, go;
                gi.v = gp[0]; gf.v = gp[1]; gG.v = gp[2]; go.v = gp[3];
                float* cs = c2s + 2 * s;
                float h0 = cellstep(gi.f.x, gf.f.x, gG.f.x, go.f.x, cs[0]);
                float h1 = cellstep(gi.f.y, gf.f.y, gG.f.y, go.f.y, cs[1]);
                hcH[rpg * 106 + 52 + au] = __floats2half2_rn(h0, h1);
            }
            acc[0][0].v = acc[0][1].v = acc[0][2].v = acc[0][3].v = pk2(bs1[2 * c2]);
            acc[1][0].v = acc[1][1].v = acc[1][2].v = acc[1][3].v = pk2(bs1[2 * c2 + 1]);
            gate_accum(w1p, hb, 0, 26, acc);    // reads h1_t + x_{t+1}
            gbuf_store(gbA, c2, rh, acc);
        }
        __syncthreads();
    }

    // epilog: y_{T-1}
    if (yw) {
        const __half2* h2p = hcH + (yr >> 1) * 106 + 52;
        const int sel = yr & 1;
        float y = ybias;
        #pragma unroll 3
        for (int u = 0; u < HH; u++) {
            float2 f = __half22float2(h2p[u]);
            y += (sel ? f.y : f.x) * wls[u];
        }
        out[(row0 + yr) * TTN + (TTN - 1)] = y;
    }
}

extern "C" void kernel_launch(void* const* d_in, const int* in_sizes, int n_in,
                              void* d_out, int out_size) {
    const float* input = (const float*)d_in[0];
    const float* Wih1  = (const float*)d_in[1];
    const float* Whh1  = (const float*)d_in[2];
    const float* bih1  = (const float*)d_in[3];
    const float* bhh1  = (const float*)d_in[4];
    const float* Wih2  = (const float*)d_in[5];
    const float* Whh2  = (const float*)d_in[6];
    const float* bih2  = (const float*)d_in[7];
    const float* bhh2  = (const float*)d_in[8];
    const float* Wlin  = (const float*)d_in[9];
    const float* blin  = (const float*)d_in[10];
    float* out = (float*)d_out;

    const size_t smem = SM_TOT * sizeof(float);   // ~165 KB
    cudaFuncSetAttribute(lstm2_kernel, cudaFuncAttributeMaxDynamicSharedMemorySize, (int)smem);

    lstm2_kernel<<<NBLK, NTHR, smem>>>(input, Wih1, Whh1, bih1, bhh1,
                                       Wih2, Whh2, bih2, bhh2, Wlin, blin, out);
}

// round 11
// speedup vs baseline: 2.1564x; 2.1564x over previous
#include <cuda_runtime.h>

// Fixed problem shape
#define BB   2048
#define TTN  2048
#define HH   51
#define RPB  16          // batch rows per block
#define NBLK 128
#define NTHR 128
#define GT   102         // gate threads: unit u=tid>>1 (0..50), row-half rh=tid&1 (8 rows)

typedef unsigned long long u64;

__device__ __forceinline__ u64 pk2(float a) {
    u64 r; asm("mov.b64 %0, {%1, %1};" : "=l"(r) : "f"(a)); return r;
}
__device__ __forceinline__ u64 fma2(u64 a, u64 b, u64 c) {
    u64 d; asm("fma.rn.f32x2 %0, %1, %2, %3;" : "=l"(d) : "l"(a), "l"(b), "l"(c)); return d;
}
union U2 { u64 v; float2 f; };

__device__ __forceinline__ float tanhap(float x) {
    float y; asm("tanh.approx.f32 %0, %1;" : "=f"(y) : "f"(x)); return y;
}
__device__ __forceinline__ float sigap(float x) {
    return fmaf(0.5f, tanhap(0.5f * x), 0.5f);
}
__device__ __forceinline__ float cellstep(float gi, float gf, float gg, float go, float& c) {
    float cn = sigap(gf) * c + sigap(gi) * tanhap(gg);
    c = cn;
    return sigap(go) * tanhap(cn);
}

// ---------------- smem layout (float offsets) ----------------
// W1s : [k 0..51][u*4+g] row 208 fl; k<51 = Whh1[:,k], k=51 = Wih1  (gates1_{t+1})
// W2s : [k 0..102][u*4+g]; k<51 = Wih2[:,k] (h1), k=51 = 0 (x slot), 52..102 = Whh2[:,k-52]
// hcat: [k 0..102][row 0..15 pad 20]; k: 0..50 h1_t, 51 x_{t+1}, 52..102 h2_{t-1}
#define W1S_OFF 0                        // 52*208 = 10816
#define W2S_OFF 10816                    // 103*208 = 21424
#define HC_OFF  32240                    // 103*20 = 2060
#define BS1_OFF 34300                    // 208
#define BS2_OFF 34508                    // 208
#define WLS_OFF 34716                    // 64
#define SM_TOT  34780                    // 139,120 B

__global__ __launch_bounds__(NTHR, 1)
void lstm2_kernel(const float* __restrict__ input,
                  const float* __restrict__ Wih1, const float* __restrict__ Whh1,
                  const float* __restrict__ bih1, const float* __restrict__ bhh1,
                  const float* __restrict__ Wih2, const float* __restrict__ Whh2,
                  const float* __restrict__ bih2, const float* __restrict__ bhh2,
                  const float* __restrict__ Wlin, const float* __restrict__ blin,
                  float* __restrict__ out)
{
    extern __shared__ float sm[];
    const int tid  = threadIdx.x;
    const int row0 = blockIdx.x * RPB;

    float*  hcf  = sm + HC_OFF;
    float*  bs1  = sm + BS1_OFF;
    float*  bs2  = sm + BS2_OFF;
    float*  wls  = sm + WLS_OFF;
    const float4* W1s4 = reinterpret_cast<const float4*>(sm + W1S_OFF);
    const float4* W2s4 = reinterpret_cast<const float4*>(sm + W2S_OFF);

    // ---------------- staging ----------------
    for (int q = tid; q < 52 * 204; q += NTHR) {
        int k = q / 204, c = q % 204;
        int u = c >> 2, g = c & 3, j = g * HH + u;
        sm[W1S_OFF + k * 208 + c] = (k < HH) ? Whh1[j * HH + k] : Wih1[j];
    }
    for (int q = tid; q < 103 * 204; q += NTHR) {
        int k = q / 204, c = q % 204;
        int u = c >> 2, g = c & 3, j = g * HH + u;
        float v;
        if (k < HH)       v = Wih2[j * HH + k];
        else if (k == HH) v = 0.0f;
        else              v = Whh2[j * HH + (k - 52)];
        sm[W2S_OFF + k * 208 + c] = v;
    }
    for (int c = tid; c < 208; c += NTHR) {
        if (c < 204) {
            int u = c >> 2, g = c & 3, j = g * HH + u;
            bs1[c] = bih1[j] + bhh1[j];
            bs2[c] = bih2[j] + bhh2[j];
        } else { bs1[c] = 0.f; bs2[c] = 0.f; }
    }
    if (tid < HH) wls[tid] = Wlin[tid];
    for (int i = tid; i < 103 * 20; i += NTHR) hcf[i] = 0.0f;
    __syncthreads();
    if (tid < RPB) hcf[51 * 20 + tid] = input[(row0 + tid) * TTN];   // x_0
    __syncthreads();

    // ---------------- roles ----------------
    const bool cw = (tid < GT);
    const int  u = tid >> 1, rh = tid & 1, rbase = rh * 8;
    const bool yw = (tid >= 102 && tid < 118);
    const int  yr = tid - 102;
    const bool xw = (tid >= 118 && tid < 126);
    const int  xi = tid - 118;

    float c1s[8] = {0,0,0,0,0,0,0,0};
    float c2s[8] = {0,0,0,0,0,0,0,0};
    U2 acc1[4][4], acc2[4][4];     // [gate][rowpair]
    const float ybias = blin[0];

    float2 xa = make_float2(0.f, 0.f);   // x_{t+1} prefetch (2 rows per x-thread)
    if (xw && TTN > 1)
        xa = make_float2(input[(row0 + 2 * xi) * TTN + 1],
                         input[(row0 + 2 * xi + 1) * TTN + 1]);

    // ---------------- prolog: L1 gates for t=0 (h1=0, x_0) ----------------
    if (cw) {
        #pragma unroll
        for (int g = 0; g < 4; g++) {
            u64 b = pk2(bs1[u * 4 + g]);
            acc1[g][0].v = b; acc1[g][1].v = b; acc1[g][2].v = b; acc1[g][3].v = b;
        }
        for (int k = 0; k < 52; k++) {
            float4 w1 = W1s4[k * 52 + u];
            const ulonglong2* hp = reinterpret_cast<const ulonglong2*>(&hcf[k * 20 + rbase]);
            ulonglong2 hA = hp[0], hB = hp[1];
            u64 wg;
            wg = pk2(w1.x);
            acc1[0][0].v = fma2(wg, hA.x, acc1[0][0].v); acc1[0][1].v = fma2(wg, hA.y, acc1[0][1].v);
            acc1[0][2].v = fma2(wg, hB.x, acc1[0][2].v); acc1[0][3].v = fma2(wg, hB.y, acc1[0][3].v);
            wg = pk2(w1.y);
            acc1[1][0].v = fma2(wg, hA.x, acc1[1][0].v); acc1[1][1].v = fma2(wg, hA.y, acc1[1][1].v);
            acc1[1][2].v = fma2(wg, hB.x, acc1[1][2].v); acc1[1][3].v = fma2(wg, hB.y, acc1[1][3].v);
            wg = pk2(w1.z);
            acc1[2][0].v = fma2(wg, hA.x, acc1[2][0].v); acc1[2][1].v = fma2(wg, hA.y, acc1[2][1].v);
            acc1[2][2].v = fma2(wg, hB.x, acc1[2][2].v); acc1[2][3].v = fma2(wg, hB.y, acc1[2][3].v);
            wg = pk2(w1.w);
            acc1[3][0].v = fma2(wg, hA.x, acc1[3][0].v); acc1[3][1].v = fma2(wg, hA.y, acc1[3][1].v);
            acc1[3][2].v = fma2(wg, hB.x, acc1[3][2].v); acc1[3][3].v = fma2(wg, hB.y, acc1[3][3].v);
        }
    }
    __syncthreads();

    // ---------------- main loop: 2 barriers/step ----------------
    for (int t = 0; t < TTN; t++) {
        // === ACT: act1(acc1)->h1_t; act2(acc2)->h2_{t-1}; publish x_{t+1} ===
        if (cw) {
            float h1n[8], h2n[8];
            #pragma unroll
            for (int p = 0; p < 4; p++) {
                float2 gi = acc1[0][p].f, gf = acc1[1][p].f, gG = acc1[2][p].f, go = acc1[3][p].f;
                h1n[2*p]   = cellstep(gi.x, gf.x, gG.x, go.x, c1s[2*p]);
                h1n[2*p+1] = cellstep(gi.y, gf.y, gG.y, go.y, c1s[2*p+1]);
            }
            *reinterpret_cast<float4*>(&hcf[u * 20 + rbase])     = make_float4(h1n[0], h1n[1], h1n[2], h1n[3]);
            *reinterpret_cast<float4*>(&hcf[u * 20 + rbase + 4]) = make_float4(h1n[4], h1n[5], h1n[6], h1n[7]);
            if (t > 0) {
                #pragma unroll
                for (int p = 0; p < 4; p++) {
                    float2 gi = acc2[0][p].f, gf = acc2[1][p].f, gG = acc2[2][p].f, go = acc2[3][p].f;
                    h2n[2*p]   = cellstep(gi.x, gf.x, gG.x, go.x, c2s[2*p]);
                    h2n[2*p+1] = cellstep(gi.y, gf.y, gG.y, go.y, c2s[2*p+1]);
                }
                *reinterpret_cast<float4*>(&hcf[(52 + u) * 20 + rbase])     = make_float4(h2n[0], h2n[1], h2n[2], h2n[3]);
                *reinterpret_cast<float4*>(&hcf[(52 + u) * 20 + rbase + 4]) = make_float4(h2n[4], h2n[5], h2n[6], h2n[7]);
            }
        } else if (xw && t + 1 < TTN) {
            hcf[51 * 20 + 2 * xi]     = xa.x;           // publish x_{t+1}
            hcf[51 * 20 + 2 * xi + 1] = xa.y;
            if (t + 2 < TTN)
                xa = make_float2(input[(row0 + 2 * xi) * TTN + t + 2],
                                 input[(row0 + 2 * xi + 1) * TTN + t + 2]);
        }
        __syncthreads();

        // === GEMM: acc2 = W2*[h1_t, h2_{t-1}];  acc1 = W1*[h1_t, x_{t+1}] ===
        if (cw) {
            #pragma unroll
            for (int g = 0; g < 4; g++) {
                u64 b1 = pk2(bs1[u * 4 + g]);
                u64 b2 = pk2(bs2[u * 4 + g]);
                acc1[g][0].v = b1; acc1[g][1].v = b1; acc1[g][2].v = b1; acc1[g][3].v = b1;
                acc2[g][0].v = b2; acc2[g][1].v = b2; acc2[g][2].v = b2; acc2[g][3].v = b2;
            }
            #pragma unroll 4
            for (int k = 0; k < 52; k++) {          // shared h: h1 (0..50) + x (51)
                float4 w1 = W1s4[k * 52 + u];
                float4 w2 = W2s4[k * 52 + u];
                const ulonglong2* hp = reinterpret_cast<const ulonglong2*>(&hcf[k * 20 + rbase]);
                ulonglong2 hA = hp[0], hB = hp[1];
                u64 wg;
                wg = pk2(w1.x);
                acc1[0][0].v = fma2(wg, hA.x, acc1[0][0].v); acc1[0][1].v = fma2(wg, hA.y, acc1[0][1].v);
                acc1[0][2].v = fma2(wg, hB.x, acc1[0][2].v); acc1[0][3].v = fma2(wg, hB.y, acc1[0][3].v);
                wg = pk2(w1.y);
                acc1[1][0].v = fma2(wg, hA.x, acc1[1][0].v); acc1[1][1].v = fma2(wg, hA.y, acc1[1][1].v);
                acc1[1][2].v = fma2(wg, hB.x, acc1[1][2].v); acc1[1][3].v = fma2(wg, hB.y, acc1[1][3].v);
                wg = pk2(w1.z);
                acc1[2][0].v = fma2(wg, hA.x, acc1[2][0].v); acc1[2][1].v = fma2(wg, hA.y, acc1[2][1].v);
                acc1[2][2].v = fma2(wg, hB.x, acc1[2][2].v); acc1[2][3].v = fma2(wg, hB.y, acc1[2][3].v);
                wg = pk2(w1.w);
                acc1[3][0].v = fma2(wg, hA.x, acc1[3][0].v); acc1[3][1].v = fma2(wg, hA.y, acc1[3][1].v);
                acc1[3][2].v = fma2(wg, hB.x, acc1[3][2].v); acc1[3][3].v = fma2(wg, hB.y, acc1[3][3].v);
                wg = pk2(w2.x);
                acc2[0][0].v = fma2(wg, hA.x, acc2[0][0].v); acc2[0][1].v = fma2(wg, hA.y, acc2[0][1].v);
                acc2[0][2].v = fma2(wg, hB.x, acc2[0][2].v); acc2[0][3].v = fma2(wg, hB.y, acc2[0][3].v);
                wg = pk2(w2.y);
                acc2[1][0].v = fma2(wg, hA.x, acc2[1][0].v); acc2[1][1].v = fma2(wg, hA.y, acc2[1][1].v);
                acc2[1][2].v = fma2(wg, hB.x, acc2[1][2].v); acc2[1][3].v = fma2(wg, hB.y, acc2[1][3].v);
                wg = pk2(w2.z);
                acc2[2][0].v = fma2(wg, hA.x, acc2[2][0].v); acc2[2][1].v = fma2(wg, hA.y, acc2[2][1].v);
                acc2[2][2].v = fma2(wg, hB.x, acc2[2][2].v); acc2[2][3].v = fma2(wg, hB.y, acc2[2][3].v);
                wg = pk2(w2.w);
                acc2[3][0].v = fma2(wg, hA.x, acc2[3][0].v); acc2[3][1].v = fma2(wg, hA.y, acc2[3][1].v);
                acc2[3][2].v = fma2(wg, hB.x, acc2[3][2].v); acc2[3][3].v = fma2(wg, hB.y, acc2[3][3].v);
            }
            #pragma unroll 4
            for (int k = 52; k < 103; k++) {        // h2_{t-1} part: W2 only
                float4 w2 = W2s4[k * 52 + u];
                const ulonglong2* hp = reinterpret_cast<const ulonglong2*>(&hcf[k * 20 + rbase]);
                ulonglong2 hA = hp[0], hB = hp[1];
                u64 wg;
                wg = pk2(w2.x);
                acc2[0][0].v = fma2(wg, hA.x, acc2[0][0].v); acc2[0][1].v = fma2(wg, hA.y, acc2[0][1].v);
                acc2[0][2].v = fma2(wg, hB.x, acc2[0][2].v); acc2[0][3].v = fma2(wg, hB.y, acc2[0][3].v);
                wg = pk2(w2.y);
                acc2[1][0].v = fma2(wg, hA.x, acc2[1][0].v); acc2[1][1].v = fma2(wg, hA.y, acc2[1][1].v);
                acc2[1][2].v = fma2(wg, hB.x, acc2[1][2].v); acc2[1][3].v = fma2(wg, hB.y, acc2[1][3].v);
                wg = pk2(w2.z);
                acc2[2][0].v = fma2(wg, hA.x, acc2[2][0].v); acc2[2][1].v = fma2(wg, hA.y, acc2[2][1].v);
                acc2[2][2].v = fma2(wg, hB.x, acc2[2][2].v); acc2[2][3].v = fma2(wg, hB.y, acc2[2][3].v);
                wg = pk2(w2.w);
                acc2[3][0].v = fma2(wg, hA.x, acc2[3][0].v); acc2[3][1].v = fma2(wg, hA.y, acc2[3][1].v);
                acc2[3][2].v = fma2(wg, hB.x, acc2[3][2].v); acc2[3][3].v = fma2(wg, hB.y, acc2[3][3].v);
            }
        } else if (yw && t > 0) {
            // y_{t-1} from h2_{t-1} (stable during GEMM; GEMM also reads it)
            float y = ybias;
            #pragma unroll 3
            for (int k = 0; k < HH; k++)
                y += hcf[(52 + k) * 20 + yr] * wls[k];
            out[(row0 + yr) * TTN + (t - 1)] = y;
        }
        __syncthreads();
    }

    // ---------------- epilog: act2 for t=TTN-1, then y_{TTN-1} ----------------
    if (cw) {
        float h2n[8];
        #pragma unroll
        for (int p = 0; p < 4; p++) {
            float2 gi = acc2[0][p].f, gf = acc2[1][p].f, gG = acc2[2][p].f, go = acc2[3][p].f;
            h2n[2*p]   = cellstep(gi.x, gf.x, gG.x, go.x, c2s[2*p]);
            h2n[2*p+1] = cellstep(gi.y, gf.y, gG.y, go.y, c2s[2*p+1]);
        }
        *reinterpret_cast<float4*>(&hcf[(52 + u) * 20 + rbase])     = make_float4(h2n[0], h2n[1], h2n[2], h2n[3]);
        *reinterpret_cast<float4*>(&hcf[(52 + u) * 20 + rbase + 4]) = make_float4(h2n[4], h2n[5], h2n[6], h2n[7]);
    }
    __syncthreads();
    if (yw) {
        float y = ybias;
        #pragma unroll 3
        for (int k = 0; k < HH; k++)
            y += hcf[(52 + k) * 20 + yr] * wls[k];
        out[(row0 + yr) * TTN + (TTN - 1)] = y;
    }
}

extern "C" void kernel_launch(void* const* d_in, const int* in_sizes, int n_in,
                              void* d_out, int out_size) {
    const float* input = (const float*)d_in[0];
    const float* Wih1  = (const float*)d_in[1];
    const float* Whh1  = (const float*)d_in[2];
    const float* bih1  = (const float*)d_in[3];
    const float* bhh1  = (const float*)d_in[4];
    const float* Wih2  = (const float*)d_in[5];
    const float* Whh2  = (const float*)d_in[6];
    const float* bih2  = (const float*)d_in[7];
    const float* bhh2  = (const float*)d_in[8];
    const float* Wlin  = (const float*)d_in[9];
    const float* blin  = (const float*)d_in[10];
    float* out = (float*)d_out;

    const size_t smem = SM_TOT * sizeof(float);   // ~139 KB
    cudaFuncSetAttribute(lstm2_kernel, cudaFuncAttributeMaxDynamicSharedMemorySize, (int)smem);

    lstm2_kernel<<<NBLK, NTHR, smem>>>(input, Wih1, Whh1, bih1, bhh1,
                                       Wih2, Whh2, bih2, bhh2, Wlin, blin, out);
}